// round 7
// baseline (speedup 1.0000x reference)
#include <cuda_runtime.h>
#include <math.h>

// Problem constants (fixed shapes from setup_inputs)
#define D 64
#define R 64
#define T 4096
#define B 8
#define NTOK (B * T)                  // 32768
#define STRENGTH 0.1f
#define SC 0.17677669529663687f       // sqrt(2/64)

#define K1_BLOCKS 256                 // 8 batches * 32 chunks of 128 tokens
#define K1_CHUNKS 32                  // per batch (128 tokens each)
#define STRIDE 68                     // smem row stride (floats): 16B-aligned

// dynamic smem layout (floats)
#define OFF_W   0                     // [128][68] combined weights (persistent)
#define OFF_C   (128 * STRIDE)        // [64][68]  coords (per sub-pass)
#define OFF_P   (192 * STRIDE)        // [16][64]  per-token-group partials
#define OFF_B1  (OFF_P + 1024)        // [64]
#define OFF_W2  (OFF_B1 + 64)         // [64]
#define OFF_BR  (OFF_W2 + 64)         // [64]
#define SMEM_FLOATS (OFF_BR + 64)
#define SMEM_BYTES  (SMEM_FLOATS * 4) // 57088 B -> 2 CTAs/SM

// Scratch (device globals — no allocation)
__device__ float g_phi[(size_t)NTOK * R];        // 8 MB (L2-resident at use)
__device__ float g_partial[K1_BLOCKS * R];
__device__ float g_phisum[B * R];

// ---------------------------------------------------------------------------
// K1: tiled GEMM coords @ [w1^T | W], 128 tokens/block in two sub-passes.
// Thread tile: 4 tokens (tg) x 8 rows (rg + 16*i; i<4 = w1, i>=4 = W).
// (unchanged from R6 — verified 33 us, regs 122, no spills)
// ---------------------------------------------------------------------------
__global__ __launch_bounds__(256) void k1_phi_mass(
    const float* __restrict__ coords, const float* __restrict__ w1,
    const float* __restrict__ b1, const float* __restrict__ w2,
    const float* __restrict__ b2, const float* __restrict__ W,
    const float* __restrict__ bR)
{
    extern __shared__ float sm[];
    float* s_w    = sm + OFF_W;
    float* s_c    = sm + OFF_C;
    float* s_part = sm + OFF_P;
    float* s_b1   = sm + OFF_B1;
    float* s_w2   = sm + OFF_W2;
    float* s_bR   = sm + OFF_BR;

    const int tid = threadIdx.x;
    const int bb = blockIdx.x >> 5, chunk = blockIdx.x & 31;
    const int tokBase0 = bb * T + chunk * 128;

    for (int idx = tid; idx < 4096; idx += 256) {
        int r = idx >> 6, k = idx & 63;
        s_w[r * STRIDE + k] = w1[idx];
    }
    for (int idx = tid; idx < 4096; idx += 256) {
        int k = idx >> 6, r = idx & 63;
        s_w[(64 + r) * STRIDE + k] = W[idx];
    }
    if (tid < 64) { s_b1[tid] = b1[tid]; s_w2[tid] = w2[tid]; s_bR[tid] = bR[tid]; }

    const int tg = tid >> 4;
    const int rg = tid & 15;
    const float b2v = __ldg(b2);
    const float* cb = s_c + (tg * 4) * STRIDE;
    const float* wb = s_w + rg * STRIDE;

    float part[4] = {0.f, 0.f, 0.f, 0.f};

    for (int sub = 0; sub < 2; ++sub) {
        const int tokBase = tokBase0 + sub * 64;

        __syncthreads();
        for (int idx = tid; idx < 4096; idx += 256) {
            int t = idx >> 6, k = idx & 63;
            s_c[t * STRIDE + k] = coords[(size_t)(tokBase + t) * D + k];
        }
        __syncthreads();

        float acc[4][8];
        #pragma unroll
        for (int j = 0; j < 4; ++j)
            #pragma unroll
            for (int i = 0; i < 8; ++i) acc[j][i] = 0.f;

        #pragma unroll 4
        for (int k4 = 0; k4 < 16; ++k4) {
            float4 c[4], w[8];
            #pragma unroll
            for (int j = 0; j < 4; ++j)
                c[j] = *(const float4*)(cb + j * STRIDE + k4 * 4);
            #pragma unroll
            for (int i = 0; i < 8; ++i)
                w[i] = *(const float4*)(wb + i * 16 * STRIDE + k4 * 4);
            #pragma unroll
            for (int j = 0; j < 4; ++j)
                #pragma unroll
                for (int i = 0; i < 8; ++i) {
                    acc[j][i] = fmaf(c[j].x, w[i].x, acc[j][i]);
                    acc[j][i] = fmaf(c[j].y, w[i].y, acc[j][i]);
                    acc[j][i] = fmaf(c[j].z, w[i].z, acc[j][i]);
                    acc[j][i] = fmaf(c[j].w, w[i].w, acc[j][i]);
                }
        }

        #pragma unroll
        for (int j = 0; j < 4; ++j) {
            float mp = 0.f;
            #pragma unroll
            for (int i = 0; i < 4; ++i) {
                const int row = rg + i * 16;
                const float h = fmaxf(acc[j][i] + s_b1[row], 0.f);
                mp = fmaf(h, s_w2[row], mp);
            }
            mp += __shfl_xor_sync(0xffffffffu, mp, 8);
            mp += __shfl_xor_sync(0xffffffffu, mp, 4);
            mp += __shfl_xor_sync(0xffffffffu, mp, 2);
            mp += __shfl_xor_sync(0xffffffffu, mp, 1);
            const float x = mp + b2v;
            const float mass = fmaxf(x, 0.f) + __logf(1.f + __expf(-fabsf(x)));

            const size_t gbase = (size_t)(tokBase + tg * 4 + j) * R;
            #pragma unroll
            for (int i = 0; i < 4; ++i) {
                const int row = rg + i * 16;
                const float ph = SC * __cosf(acc[j][i + 4] + s_bR[row]);
                g_phi[gbase + row] = ph;
                part[i] = fmaf(mass, ph, part[i]);
            }
        }
    }

    __syncthreads();
    #pragma unroll
    for (int i = 0; i < 4; ++i)
        s_part[tg * 64 + rg + i * 16] = part[i];
    __syncthreads();

    if (tid < 64) {
        float s = 0.f;
        #pragma unroll
        for (int t = 0; t < 16; ++t) s += s_part[t * 64 + tid];
        g_partial[blockIdx.x * 64 + tid] = s;
    }
}

// ---------------------------------------------------------------------------
// K2: phisum[b][r] = sum over 32 chunk partials (deterministic, tiny)
// ---------------------------------------------------------------------------
__global__ void k2_phisum()
{
    const int bb = blockIdx.x;        // 8 blocks
    const int r = threadIdx.x;        // 64 threads
    float s = 0.f;
    #pragma unroll
    for (int c = 0; c < K1_CHUNKS; ++c)
        s += g_partial[(bb * K1_CHUNKS + c) * 64 + r];
    g_phisum[bb * 64 + r] = s;
}

// ---------------------------------------------------------------------------
// K4a: bulk copy of G -> out, SKIPPING the 64 diagonal-containing float4s
// per 64x64 tile. Predicate: f4-index `within` holds a diag element iff
// (within & 15) == (within >> 6). No dependency on anything.
// ---------------------------------------------------------------------------
__global__ __launch_bounds__(256) void k4a_copy(const float4* __restrict__ G4,
                                                float4* __restrict__ O4)
{
    const unsigned tile = blockIdx.x;
    const size_t base = (size_t)tile * 1024;
    const unsigned t = threadIdx.x;
    const unsigned tlow = t & 15u;

    #pragma unroll
    for (int k = 0; k < 4; ++k) {
        const unsigned within = k * 256u + t;
        if (tlow != (within >> 6)) {          // not a diag f4
            float4 v = __ldcs(G4 + base + within);
            __stcs(O4 + base + within, v);
        }
    }
}

// ---------------------------------------------------------------------------
// K4b: per-tile grav + write the 64 diagonal float4s.
// Warp per tile: grav = STRENGTH * dot(phi[tile], phisum[batch]) (shfl-reduce),
// then lane handles rows i=lane and i=lane+32: f4 at within=16i+(i>>2),
// out f4 = G f4 with component (i&3) += grav.
// ---------------------------------------------------------------------------
__global__ __launch_bounds__(256) void k4b_diag(const float4* __restrict__ G4,
                                                 float4* __restrict__ O4)
{
    const int lane = threadIdx.x & 31, warp = threadIdx.x >> 5;
    const unsigned tile = blockIdx.x * 8u + warp;      // 4096 blocks * 8 warps
    const unsigned bb = tile >> 12;                    // 4096 tiles per batch

    const float* ph = g_phi + (size_t)tile * R;
    const float* ps = g_phisum + bb * 64;
    float v = fmaf(ph[lane], ps[lane], ph[lane + 32] * ps[lane + 32]);
    v += __shfl_xor_sync(0xffffffffu, v, 16);
    v += __shfl_xor_sync(0xffffffffu, v, 8);
    v += __shfl_xor_sync(0xffffffffu, v, 4);
    v += __shfl_xor_sync(0xffffffffu, v, 2);
    v += __shfl_xor_sync(0xffffffffu, v, 1);
    const float gv = STRENGTH * v;                     // uniform across warp

    const size_t base = (size_t)tile * 1024;
    #pragma unroll
    for (int half = 0; half < 2; ++half) {
        const int i = lane + half * 32;
        const unsigned within = (unsigned)(i * 16 + (i >> 2));
        float4 g = __ldcs(G4 + base + within);
        const int d = i & 3;
        if      (d == 0) g.x += gv;
        else if (d == 1) g.y += gv;
        else if (d == 2) g.z += gv;
        else             g.w += gv;
        __stcs(O4 + base + within, g);
    }
}

// ---------------------------------------------------------------------------
extern "C" void kernel_launch(void* const* d_in, const int* in_sizes, int n_in,
                              void* d_out, int out_size)
{
    const float* G      = (const float*)d_in[0];
    const float* coords = (const float*)d_in[1];
    const float* w1     = (const float*)d_in[2];
    const float* b1     = (const float*)d_in[3];
    const float* w2     = (const float*)d_in[4];
    const float* b2     = (const float*)d_in[5];
    const float* W      = (const float*)d_in[6];
    const float* bR     = (const float*)d_in[7];
    float* out = (float*)d_out;

    cudaFuncSetAttribute(k1_phi_mass,
                         cudaFuncAttributeMaxDynamicSharedMemorySize, SMEM_BYTES);

    // Fork-join inside stream capture: side stream runs the grav pipeline
    // concurrently with the dependency-free bulk copy on the main stream.
    // (Handles are intentionally not destroyed: destroying a stream/event
    //  that participates in an in-progress capture would invalidate it.)
    cudaStream_t s;
    cudaStreamCreateWithFlags(&s, cudaStreamNonBlocking);
    cudaEvent_t e0, e1;
    cudaEventCreateWithFlags(&e0, cudaEventDisableTiming);
    cudaEventCreateWithFlags(&e1, cudaEventDisableTiming);

    cudaEventRecord(e0, 0);
    cudaStreamWaitEvent(s, e0, 0);                     // fork

    k1_phi_mass<<<K1_BLOCKS, 256, SMEM_BYTES, s>>>(coords, w1, b1, w2, b2, W, bR);
    k2_phisum<<<B, 64, 0, s>>>();
    k4b_diag<<<NTOK / 8, 256, 0, s>>>((const float4*)G, (float4*)out);

    k4a_copy<<<NTOK, 256>>>((const float4*)G, (float4*)out);   // main stream

    cudaEventRecord(e1, s);
    cudaStreamWaitEvent(0, e1, 0);                     // join
}

// round 8
// speedup vs baseline: 1.9017x; 1.9017x over previous
#include <cuda_runtime.h>
#include <math.h>

// Problem constants (fixed shapes from setup_inputs)
#define D 64
#define R 64
#define T 4096
#define B 8
#define NTOK (B * T)                  // 32768
#define STRENGTH 0.1f
#define SC 0.17677669529663687f       // sqrt(2/64)

#define K1_BLOCKS 256                 // 8 batches * 32 chunks of 128 tokens
#define K1_CHUNKS 32                  // per batch (128 tokens each)
#define STRIDE 68                     // smem row stride (floats): 16B-aligned

// dynamic smem layout (floats)
#define OFF_W   0                     // [128][68] combined weights (persistent)
#define OFF_C   (128 * STRIDE)        // [128][68] coords (all 128 tokens)
#define OFF_P   (256 * STRIDE)        // [16][64]  per-token-group partials
#define OFF_B1  (OFF_P + 1024)        // [64]
#define OFF_W2  (OFF_B1 + 64)         // [64]
#define OFF_BR  (OFF_W2 + 64)         // [64]
#define SMEM_FLOATS (OFF_BR + 64)
#define SMEM_BYTES  (SMEM_FLOATS * 4) // 74,496 B -> 2 CTAs/SM (regs bind anyway)

// Scratch (device globals — no allocation)
__device__ float g_phi[(size_t)NTOK * R];        // 8 MB (L2-resident at use)
__device__ float g_partial[K1_BLOCKS * R];
__device__ float g_phisum[B * R];

// ---------------------------------------------------------------------------
// K1: tiled GEMM coords @ [w1^T | W], 128 tokens/block in two sub-passes.
// Thread tile: 4 tokens (tg) x 8 rows (rg + 16*i; i<4 = w1, i>=4 = W).
// All 128 tokens' coords staged once; no mid-kernel re-staging sync.
// ---------------------------------------------------------------------------
__global__ __launch_bounds__(256) void k1_phi_mass(
    const float* __restrict__ coords, const float* __restrict__ w1,
    const float* __restrict__ b1, const float* __restrict__ w2,
    const float* __restrict__ b2, const float* __restrict__ W,
    const float* __restrict__ bR)
{
    extern __shared__ float sm[];
    float* s_w    = sm + OFF_W;
    float* s_c    = sm + OFF_C;
    float* s_part = sm + OFF_P;
    float* s_b1   = sm + OFF_B1;
    float* s_w2   = sm + OFF_W2;
    float* s_bR   = sm + OFF_BR;

    const int tid = threadIdx.x;
    const int bb = blockIdx.x >> 5, chunk = blockIdx.x & 31;
    const int tokBase0 = bb * T + chunk * 128;

    // --- stage weights + all 128 tokens of coords ---
    for (int idx = tid; idx < 4096; idx += 256) {
        int r = idx >> 6, k = idx & 63;
        s_w[r * STRIDE + k] = w1[idx];
    }
    for (int idx = tid; idx < 4096; idx += 256) {
        int k = idx >> 6, r = idx & 63;
        s_w[(64 + r) * STRIDE + k] = W[idx];
    }
    for (int idx = tid; idx < 8192; idx += 256) {
        int t = idx >> 6, k = idx & 63;
        s_c[t * STRIDE + k] = coords[(size_t)(tokBase0 + t) * D + k];
    }
    if (tid < 64) { s_b1[tid] = b1[tid]; s_w2[tid] = w2[tid]; s_bR[tid] = bR[tid]; }
    __syncthreads();

    const int tg = tid >> 4;
    const int rg = tid & 15;
    const float b2v = __ldg(b2);
    const float* wb = s_w + rg * STRIDE;

    float part[4] = {0.f, 0.f, 0.f, 0.f};

    #pragma unroll 1
    for (int sub = 0; sub < 2; ++sub) {
        const int tokBase = tokBase0 + sub * 64;
        const float* cb = s_c + (sub * 64 + tg * 4) * STRIDE;

        float acc[4][8];
        #pragma unroll
        for (int j = 0; j < 4; ++j)
            #pragma unroll
            for (int i = 0; i < 8; ++i) acc[j][i] = 0.f;

        #pragma unroll 4
        for (int k4 = 0; k4 < 16; ++k4) {
            float4 c[4], w[8];
            #pragma unroll
            for (int j = 0; j < 4; ++j)
                c[j] = *(const float4*)(cb + j * STRIDE + k4 * 4);
            #pragma unroll
            for (int i = 0; i < 8; ++i)
                w[i] = *(const float4*)(wb + i * 16 * STRIDE + k4 * 4);
            #pragma unroll
            for (int j = 0; j < 4; ++j)
                #pragma unroll
                for (int i = 0; i < 8; ++i) {
                    acc[j][i] = fmaf(c[j].x, w[i].x, acc[j][i]);
                    acc[j][i] = fmaf(c[j].y, w[i].y, acc[j][i]);
                    acc[j][i] = fmaf(c[j].z, w[i].z, acc[j][i]);
                    acc[j][i] = fmaf(c[j].w, w[i].w, acc[j][i]);
                }
        }

        // --- epilogue (registers + shfl only) ---
        #pragma unroll
        for (int j = 0; j < 4; ++j) {
            float mp = 0.f;
            #pragma unroll
            for (int i = 0; i < 4; ++i) {
                const int row = rg + i * 16;
                const float h = fmaxf(acc[j][i] + s_b1[row], 0.f);
                mp = fmaf(h, s_w2[row], mp);
            }
            mp += __shfl_xor_sync(0xffffffffu, mp, 8);
            mp += __shfl_xor_sync(0xffffffffu, mp, 4);
            mp += __shfl_xor_sync(0xffffffffu, mp, 2);
            mp += __shfl_xor_sync(0xffffffffu, mp, 1);
            const float x = mp + b2v;
            const float mass = fmaxf(x, 0.f) + __logf(1.f + __expf(-fabsf(x)));

            const size_t gbase = (size_t)(tokBase + tg * 4 + j) * R;
            #pragma unroll
            for (int i = 0; i < 4; ++i) {
                const int row = rg + i * 16;
                const float ph = SC * __cosf(acc[j][i + 4] + s_bR[row]);
                g_phi[gbase + row] = ph;
                part[i] = fmaf(mass, ph, part[i]);
            }
        }
    }

    __syncthreads();
    #pragma unroll
    for (int i = 0; i < 4; ++i)
        s_part[tg * 64 + rg + i * 16] = part[i];
    __syncthreads();

    if (tid < 64) {
        float s = 0.f;
        #pragma unroll
        for (int t = 0; t < 16; ++t) s += s_part[t * 64 + tid];
        g_partial[blockIdx.x * 64 + tid] = s;
    }
}

// ---------------------------------------------------------------------------
// K2: phisum[b][r] = sum over 32 chunk partials (deterministic, tiny)
// ---------------------------------------------------------------------------
__global__ void k2_phisum()
{
    const int bb = blockIdx.x;        // 8 blocks
    const int r = threadIdx.x;        // 64 threads
    float s = 0.f;
    #pragma unroll
    for (int c = 0; c < K1_CHUNKS; ++c)
        s += g_partial[(bb * K1_CHUNKS + c) * 64 + r];
    g_phisum[bb * 64 + r] = s;
}

// ---------------------------------------------------------------------------
// K4: full-line 1 GiB stream of G with fused grav compute + diagonal add.
// Block per tile. All threads issue their 4 G loads first; warp 0 computes
// grav from phi (L2) concurrently; one sync; diag-add; full-line stores.
// ---------------------------------------------------------------------------
__global__ __launch_bounds__(256) void k4_copy(const float4* __restrict__ G4,
                                               float4* __restrict__ O4)
{
    __shared__ float s_gv;
    const unsigned tile = blockIdx.x;
    const size_t base = (size_t)tile * 1024;
    const unsigned t = threadIdx.x;

    float4 v[4];
    #pragma unroll
    for (int k = 0; k < 4; ++k)
        v[k] = __ldcs(G4 + base + k * 256u + t);

    if (t < 32) {
        const unsigned bb = tile >> 12;                // 4096 tiles per batch
        const float* ph = g_phi + (size_t)tile * R;
        const float* ps = g_phisum + bb * 64;
        float x = fmaf(ph[t], ps[t], ph[t + 32] * ps[t + 32]);
        x += __shfl_xor_sync(0xffffffffu, x, 16);
        x += __shfl_xor_sync(0xffffffffu, x, 8);
        x += __shfl_xor_sync(0xffffffffu, x, 4);
        x += __shfl_xor_sync(0xffffffffu, x, 2);
        x += __shfl_xor_sync(0xffffffffu, x, 1);
        if (t == 0) s_gv = STRENGTH * x;
    }
    __syncthreads();
    const float gv = s_gv;

    #pragma unroll
    for (int k = 0; k < 4; ++k) {
        const unsigned within = k * 256u + t;
        const int i  = (int)(within >> 4);
        const int j0 = (int)((within & 15u) << 2);
        const int d  = i - j0;
        if ((unsigned)d < 4u) {
            if      (d == 0) v[k].x += gv;
            else if (d == 1) v[k].y += gv;
            else if (d == 2) v[k].z += gv;
            else             v[k].w += gv;
        }
        __stcs(O4 + base + within, v[k]);
    }
}

// ---------------------------------------------------------------------------
extern "C" void kernel_launch(void* const* d_in, const int* in_sizes, int n_in,
                              void* d_out, int out_size)
{
    const float* G      = (const float*)d_in[0];
    const float* coords = (const float*)d_in[1];
    const float* w1     = (const float*)d_in[2];
    const float* b1     = (const float*)d_in[3];
    const float* w2     = (const float*)d_in[4];
    const float* b2     = (const float*)d_in[5];
    const float* W      = (const float*)d_in[6];
    const float* bR     = (const float*)d_in[7];
    float* out = (float*)d_out;

    cudaFuncSetAttribute(k1_phi_mass,
                         cudaFuncAttributeMaxDynamicSharedMemorySize, SMEM_BYTES);

    k1_phi_mass<<<K1_BLOCKS, 256, SMEM_BYTES>>>(coords, w1, b1, w2, b2, W, bR);
    k2_phisum<<<B, 64>>>();
    k4_copy<<<NTOK, 256>>>((const float4*)G, (float4*)out);
}